// round 13
// baseline (speedup 1.0000x reference)
#include <cuda_runtime.h>
#include <math.h>

#define Nn 100000
#define Ee 3200000
#define Hh 512
#define Bb 512
#define RWS 4
#define BM 64
#define BN 32
#define BK 32
#define KK 1024
#define KQ 256
#define NSPLIT 4
#define NCQ (KQ / BK)
#define GRID 592
#define NTHR 256
#define POOLB 512
#define EDGB (GRID - POOLB)        // 80 blocks for offsets+edges
#define OFFT ((Nn + 255) / 256)    // 391
#define EDGT (Ee / 4 / 256)        // 3125
#define FCHUNKS ((Nn * 128) / 512) // 25000

// ---------------- scratch ----------------
__device__ int   g_off[Bb + 1];
__device__ int   g_nedges[Bb];
__device__ float g_poolT[KK][Bb];
__device__ float g_pool[Bb][KK];
__device__ float g_hp[NSPLIT][Bb][Hh];
__device__ float g_w[Bb][2];
__device__ unsigned bar_cnt = 0;
__device__ volatile unsigned bar_gen = 0;

// ---------------- shared layouts ----------------
struct SmemGemm { float As[2][BK][BM]; float Ws[2][BK][BN]; };   // 24576 B
struct SmemPool { int bounds[2]; float4 sacc[128]; };
struct SmemEdge { int hist[Bb]; };
struct SmemMlp {
    float comp[RWS][4];
    float ts[RWS][Hh];
    float red[RWS][8];
    float red2[8][3];
    float sstat[RWS][3];
    float mu[RWS], rs[RWS];
    float red3[8][RWS][2];
    float raw[RWS][2];
};

// ---------------- grid barrier ----------------
__device__ __forceinline__ void gbar() {
    __threadfence();
    __syncthreads();
    if (threadIdx.x == 0) {
        unsigned g = bar_gen;
        if (atomicAdd(&bar_cnt, 1) == GRID - 1) {
            bar_cnt = 0;
            __threadfence();
            bar_gen = g + 1;
        } else {
            while (bar_gen == g) __nanosleep(64);
        }
    }
    __syncthreads();
}

// ---------------- device phase bodies ----------------
__device__ __forceinline__ int lbound(const int* __restrict__ batch, int key) {
    int lo = 0, hi = Nn;
    while (lo < hi) {
        int mid = (lo + hi) >> 1;
        if (batch[mid] < key) lo = mid + 1; else hi = mid;
    }
    return lo;
}

// pool reads use DEFAULT cache policy: the tail of the stream stays in L2
// and is consumed first by the reverse-order fuse phase.
__device__ __forceinline__ void dev_pool_task(const float* __restrict__ x,
                                              const int* __restrict__ batch,
                                              int b, int half, SmemPool* sp) {
    int t = threadIdx.x, pr = t >> 7, c = t & 127;
    if (t == 0)   sp->bounds[0] = lbound(batch, b);
    if (t == 128) sp->bounds[1] = lbound(batch, b + 1);
    __syncthreads();
    int s0 = sp->bounds[0], e0 = sp->bounds[1];

    const float4* p = ((const float4*)x) + c;
    float4 acc = make_float4(0.f, 0.f, 0.f, 0.f);
    int r = s0 + pr;
    for (; r + 14 < e0; r += 16) {
        float4 v0 = p[(size_t)(r +  0) * 128];
        float4 v1 = p[(size_t)(r +  2) * 128];
        float4 v2 = p[(size_t)(r +  4) * 128];
        float4 v3 = p[(size_t)(r +  6) * 128];
        float4 v4 = p[(size_t)(r +  8) * 128];
        float4 v5 = p[(size_t)(r + 10) * 128];
        float4 v6 = p[(size_t)(r + 12) * 128];
        float4 v7 = p[(size_t)(r + 14) * 128];
        acc.x += (v0.x + v1.x) + (v2.x + v3.x) + ((v4.x + v5.x) + (v6.x + v7.x));
        acc.y += (v0.y + v1.y) + (v2.y + v3.y) + ((v4.y + v5.y) + (v6.y + v7.y));
        acc.z += (v0.z + v1.z) + (v2.z + v3.z) + ((v4.z + v5.z) + (v6.z + v7.z));
        acc.w += (v0.w + v1.w) + (v2.w + v3.w) + ((v4.w + v5.w) + (v6.w + v7.w));
    }
    for (; r < e0; r += 2) {
        float4 v = p[(size_t)r * 128];
        acc.x += v.x; acc.y += v.y; acc.z += v.z; acc.w += v.w;
    }

    if (pr == 1) sp->sacc[c] = acc;
    __syncthreads();
    if (pr == 0) {
        float4 o = sp->sacc[c];
        float inv = 1.f / fmaxf((float)(e0 - s0), 1.f);
        float4 m = make_float4((acc.x + o.x) * inv, (acc.y + o.y) * inv,
                               (acc.z + o.z) * inv, (acc.w + o.w) * inv);
        int kb = half * Hh + 4 * c;
        g_poolT[kb + 0][b] = m.x;
        g_poolT[kb + 1][b] = m.y;
        g_poolT[kb + 2][b] = m.z;
        g_poolT[kb + 3][b] = m.w;
        *(float4*)&g_pool[b][kb] = m;
    }
}

__device__ __forceinline__ void dev_offsets_i(const int* __restrict__ batch, int i) {
    if (i >= Nn) return;
    int c = batch[i];
    int p = (i == 0) ? -1 : batch[i - 1];
    for (int b = p + 1; b <= c; b++) g_off[b] = i;
    if (i == Nn - 1) {
        for (int b = c + 1; b <= Bb; b++) g_off[b] = Nn;
    }
}

__device__ __forceinline__ void dev_edge_i(const int* __restrict__ ei,
                                           const int* __restrict__ batch,
                                           int i, int* hist) {
    const int4* src4 = (const int4*)ei;
    const int4* dst4 = (const int4*)(ei + Ee);
    int4 s = __ldg(&src4[i]);
    int4 d = __ldg(&dst4[i]);
    int sg0 = __ldg(&batch[s.x]), sg1 = __ldg(&batch[s.y]);
    int sg2 = __ldg(&batch[s.z]), sg3 = __ldg(&batch[s.w]);
    int dg0 = __ldg(&batch[d.x]), dg1 = __ldg(&batch[d.y]);
    int dg2 = __ldg(&batch[d.z]), dg3 = __ldg(&batch[d.w]);
    if (sg0 == dg0) atomicAdd(&hist[sg0], 1);
    if (sg1 == dg1) atomicAdd(&hist[sg1], 1);
    if (sg2 == dg2) atomicAdd(&hist[sg2], 1);
    if (sg3 == dg3) atomicAdd(&hist[sg3], 1);
}

__device__ __forceinline__ void dev_gemm1_task(const float* __restrict__ W1,
                                               int z, int n0, int m0, SmemGemm* sg) {
    int t = threadIdx.x;
    int tn = t & 15;
    int tm = t >> 4;
    int ak = t >> 4;
    int af = t & 15;
    int wk = t >> 3;
    int wq = t & 7;

    const float* Abase = &g_poolT[z * KQ][0];
    const float* Wbase = W1 + (size_t)z * KQ * Hh;
    size_t aIdx0 = (size_t)ak * Bb + m0 + 4 * af;
    size_t aIdx1 = (size_t)(ak + 16) * Bb + m0 + 4 * af;
    size_t wIdx  = (size_t)wk * Hh + n0 + 4 * wq;

    *(float4*)&sg->As[0][ak][4 * af]      = *(const float4*)&Abase[aIdx0];
    *(float4*)&sg->As[0][ak + 16][4 * af] = *(const float4*)&Abase[aIdx1];
    *(float4*)&sg->Ws[0][wk][4 * wq]      = *(const float4*)&Wbase[wIdx];
    __syncthreads();

    float acc[4][2];
    #pragma unroll
    for (int j = 0; j < 4; j++) { acc[j][0] = 0.f; acc[j][1] = 0.f; }

    for (int c = 0; c < NCQ; c++) {
        int nb = c & 1;
        float4 ra0, ra1, rw;
        if (c + 1 < NCQ) {
            size_t koff  = (size_t)(c + 1) * BK * Bb;
            size_t kwoff = (size_t)(c + 1) * BK * Hh;
            ra0 = *(const float4*)&Abase[koff + aIdx0];
            ra1 = *(const float4*)&Abase[koff + aIdx1];
            rw  = *(const float4*)&Wbase[kwoff + wIdx];
        }
        #pragma unroll
        for (int k = 0; k < BK; k++) {
            float4 a = *(float4*)&sg->As[nb][k][4 * tm];
            float2 w = *(float2*)&sg->Ws[nb][k][2 * tn];
            acc[0][0] += a.x * w.x; acc[0][1] += a.x * w.y;
            acc[1][0] += a.y * w.x; acc[1][1] += a.y * w.y;
            acc[2][0] += a.z * w.x; acc[2][1] += a.z * w.y;
            acc[3][0] += a.w * w.x; acc[3][1] += a.w * w.y;
        }
        if (c + 1 < NCQ) {
            __syncthreads();
            *(float4*)&sg->As[1 - nb][ak][4 * af]      = ra0;
            *(float4*)&sg->As[1 - nb][ak + 16][4 * af] = ra1;
            *(float4*)&sg->Ws[1 - nb][wk][4 * wq]      = rw;
            __syncthreads();
        }
    }

    #pragma unroll
    for (int j = 0; j < 4; j++) {
        *(float2*)&g_hp[z][m0 + 4 * tm + j][n0 + 2 * tn] = make_float2(acc[j][0], acc[j][1]);
    }
}

__device__ __forceinline__ void dev_mlp2_task(
    const float* __restrict__ W1, const float* __restrict__ b1,
    const float* __restrict__ lng, const float* __restrict__ lnb,
    const float* __restrict__ W2, const float* __restrict__ b2,
    const float* __restrict__ W3, const float* __restrict__ b3,
    int row0, SmemMlp* sl)
{
    int t = threadIdx.x;
    int lane = t & 31, wid = t >> 5;

    #pragma unroll
    for (int r = 0; r < RWS; r++) {
        int b = row0 + r;
        float2 gg = *(const float2*)&g_pool[b][2 * t];
        float2 aa = *(const float2*)&g_pool[b][Hh + 2 * t];
        float dot = gg.x * aa.x + gg.y * aa.y;
        float n2g = gg.x * gg.x + gg.y * gg.y;
        float n2a = aa.x * aa.x + aa.y * aa.y;
        #pragma unroll
        for (int o = 16; o > 0; o >>= 1) {
            dot += __shfl_down_sync(0xFFFFFFFFu, dot, o);
            n2g += __shfl_down_sync(0xFFFFFFFFu, n2g, o);
            n2a += __shfl_down_sync(0xFFFFFFFFu, n2a, o);
        }
        if (lane == 0) { sl->red2[wid][0] = dot; sl->red2[wid][1] = n2g; sl->red2[wid][2] = n2a; }
        __syncthreads();
        if (t < 3) {
            float s = 0.f;
            #pragma unroll
            for (int w = 0; w < 8; w++) s += sl->red2[w][t];
            sl->sstat[r][t] = s;
        }
        __syncthreads();
    }

    if (t < RWS) {
        int b = row0 + t;
        float cnt = (float)(g_off[b + 1] - g_off[b]);
        float ne  = (float)g_nedges[b];
        g_nedges[b] = 0;   // consume-and-reset for next replay
        float scale   = logf(cnt + 1.f) * (1.f / logf(501.0f));
        float density = ne / (cnt * (cnt - 1.f) + 1e-8f);
        float avgdeg  = ne / (cnt + 1e-8f);
        float avn     = fminf(avgdeg * 0.1f, 1.f);
        float dot = sl->sstat[t][0], n2g = sl->sstat[t][1], n2a = sl->sstat[t][2];
        float na = fmaxf(sqrtf(n2g), 1e-8f);
        float nb = fmaxf(sqrtf(n2a), 1e-8f);
        float cosv = dot / (na * nb);
        sl->comp[t][0] = scale;
        sl->comp[t][1] = density;
        sl->comp[t][2] = avn;
        sl->comp[t][3] = (1.f - cosv) * 0.5f;
    }
    __syncthreads();

    float2 w1t[4];
    #pragma unroll
    for (int j = 0; j < 4; j++)
        w1t[j] = *(const float2*)&W1[(size_t)(KK + j) * Hh + 2 * t];
    float2 bb = ((const float2*)b1)[t];
    float2 h[RWS];
    #pragma unroll
    for (int r = 0; r < RWS; r++) {
        float2 hg0 = *(const float2*)&g_hp[0][row0 + r][2 * t];
        float2 hg1 = *(const float2*)&g_hp[1][row0 + r][2 * t];
        float2 hg2 = *(const float2*)&g_hp[2][row0 + r][2 * t];
        float2 hg3 = *(const float2*)&g_hp[3][row0 + r][2 * t];
        float hx = (hg0.x + hg1.x) + (hg2.x + hg3.x) + bb.x;
        float hy = (hg0.y + hg1.y) + (hg2.y + hg3.y) + bb.y;
        #pragma unroll
        for (int j = 0; j < 4; j++) {
            hx += sl->comp[r][j] * w1t[j].x;
            hy += sl->comp[r][j] * w1t[j].y;
        }
        h[r] = make_float2(hx, hy);
    }

    #pragma unroll
    for (int r = 0; r < RWS; r++) {
        float p = h[r].x + h[r].y;
        #pragma unroll
        for (int o = 16; o > 0; o >>= 1) p += __shfl_down_sync(0xFFFFFFFFu, p, o);
        if (lane == 0) sl->red[r][wid] = p;
    }
    __syncthreads();
    if (t < RWS) {
        float s = 0.f;
        #pragma unroll
        for (int w = 0; w < 8; w++) s += sl->red[t][w];
        sl->mu[t] = s * (1.f / (float)Hh);
    }
    __syncthreads();
    #pragma unroll
    for (int r = 0; r < RWS; r++) {
        float dx = h[r].x - sl->mu[r], dy = h[r].y - sl->mu[r];
        float p = dx * dx + dy * dy;
        #pragma unroll
        for (int o = 16; o > 0; o >>= 1) p += __shfl_down_sync(0xFFFFFFFFu, p, o);
        if (lane == 0) sl->red[r][wid] = p;
    }
    __syncthreads();
    if (t < RWS) {
        float s = 0.f;
        #pragma unroll
        for (int w = 0; w < 8; w++) s += sl->red[t][w];
        sl->rs[t] = rsqrtf(s * (1.f / (float)Hh) + 1e-5f);
    }
    __syncthreads();
    {
        float2 gv = ((const float2*)lng)[t];
        float2 bv = ((const float2*)lnb)[t];
        #pragma unroll
        for (int r = 0; r < RWS; r++) {
            float vx = (h[r].x - sl->mu[r]) * sl->rs[r] * gv.x + bv.x;
            float vy = (h[r].y - sl->mu[r]) * sl->rs[r] * gv.y + bv.y;
            sl->ts[r][2 * t]     = fmaxf(vx, 0.f);
            sl->ts[r][2 * t + 1] = fmaxf(vy, 0.f);
        }
    }
    __syncthreads();

    float u[RWS];
    #pragma unroll
    for (int r = 0; r < RWS; r++) u[r] = 0.f;
    float wr[4];
    #pragma unroll
    for (int j = 0; j < 4; j++) wr[j] = W2[(size_t)j * 256 + t];
    for (int k = 0; k < Hh; k += 4) {
        float wn[4];
        if (k + 4 < Hh) {
            #pragma unroll
            for (int j = 0; j < 4; j++) wn[j] = W2[(size_t)(k + 4 + j) * 256 + t];
        }
        float ta[RWS][4];
        #pragma unroll
        for (int r = 0; r < RWS; r++) {
            float4 q = *(const float4*)&sl->ts[r][k];
            ta[r][0] = q.x; ta[r][1] = q.y; ta[r][2] = q.z; ta[r][3] = q.w;
        }
        #pragma unroll
        for (int kk = 0; kk < 4; kk++) {
            #pragma unroll
            for (int r = 0; r < RWS; r++) u[r] += ta[r][kk] * wr[kk];
        }
        #pragma unroll
        for (int j = 0; j < 4; j++) wr[j] = wn[j];
    }
    float bt = b2[t];
    #pragma unroll
    for (int r = 0; r < RWS; r++) u[r] = fmaxf(u[r] + bt, 0.f);

    float w30 = W3[2 * t], w31 = W3[2 * t + 1];
    float p0[RWS], p1[RWS];
    #pragma unroll
    for (int r = 0; r < RWS; r++) { p0[r] = u[r] * w30; p1[r] = u[r] * w31; }
    #pragma unroll
    for (int o = 16; o > 0; o >>= 1) {
        #pragma unroll
        for (int r = 0; r < RWS; r++) {
            p0[r] += __shfl_down_sync(0xFFFFFFFFu, p0[r], o);
            p1[r] += __shfl_down_sync(0xFFFFFFFFu, p1[r], o);
        }
    }
    if (lane == 0) {
        #pragma unroll
        for (int r = 0; r < RWS; r++) { sl->red3[wid][r][0] = p0[r]; sl->red3[wid][r][1] = p1[r]; }
    }
    __syncthreads();
    if (t < RWS * 2) {
        int r = t >> 1, c = t & 1;
        float s = 0.f;
        #pragma unroll
        for (int w = 0; w < 8; w++) s += sl->red3[w][r][c];
        sl->raw[r][c] = s + b3[c];
    }
    __syncthreads();
    if (t < RWS) {
        float r0 = sl->raw[t][0], r1 = sl->raw[t][1];
        float m = fmaxf(r0, r1);
        float e0 = expf(r0 - m), e1 = expf(r1 - m);
        float inv = 1.f / (e0 + e1);
        g_w[row0 + t][0] = e0 * inv;
        g_w[row0 + t][1] = e1 * inv;
    }
}

__device__ __forceinline__ void dev_fuse_chunk(const float* __restrict__ xg,
                                               const float* __restrict__ xa,
                                               const int* __restrict__ batch,
                                               float* __restrict__ out, int chunk) {
    size_t i0 = (size_t)chunk * 512 + threadIdx.x;
    size_t i1 = i0 + 256;
    int n0 = (int)(i0 >> 7);
    int n1 = (int)(i1 >> 7);
    int b0 = __ldg(&batch[n0]);
    int b1 = __ldg(&batch[n1]);
    float4 g0 = __ldcs(((const float4*)xg) + i0);
    float4 a0 = __ldcs(((const float4*)xa) + i0);
    float4 g1 = __ldcs(((const float4*)xg) + i1);
    float4 a1 = __ldcs(((const float4*)xa) + i1);
    float w00 = g_w[b0][0], w01 = g_w[b0][1];
    float w10 = g_w[b1][0], w11 = g_w[b1][1];
    float4 o0, o1;
    o0.x = w00 * g0.x + w01 * a0.x;
    o0.y = w00 * g0.y + w01 * a0.y;
    o0.z = w00 * g0.z + w01 * a0.z;
    o0.w = w00 * g0.w + w01 * a0.w;
    o1.x = w10 * g1.x + w11 * a1.x;
    o1.y = w10 * g1.y + w11 * a1.y;
    o1.z = w10 * g1.z + w11 * a1.z;
    o1.w = w10 * g1.w + w11 * a1.w;
    __stcs(((float4*)out) + i0, o0);
    __stcs(((float4*)out) + i1, o1);
}

// ---------------- persistent megakernel ----------------
__global__ void __launch_bounds__(NTHR, 4) k_mega(
    const float* __restrict__ xg, const float* __restrict__ xa,
    const int* __restrict__ edge, const int* __restrict__ batch,
    const float* __restrict__ W1, const float* __restrict__ b1,
    const float* __restrict__ lng, const float* __restrict__ lnb,
    const float* __restrict__ W2, const float* __restrict__ b2,
    const float* __restrict__ W3, const float* __restrict__ b3,
    float* __restrict__ out)
{
    __shared__ __align__(16) char sm[sizeof(SmemGemm)];
    int bid = blockIdx.x;
    int t = threadIdx.x;

    // ---- phase 1: pool (blocks 0..511) || offsets+edges (blocks 512..591)
    if (bid < POOLB) {
        SmemPool* sp = (SmemPool*)sm;
        dev_pool_task(xg, batch, bid, 0, sp);
        __syncthreads();
        dev_pool_task(xa, batch, bid, 1, sp);
    } else {
        int eb = bid - POOLB;
        for (int task = eb; task < OFFT; task += EDGB)
            dev_offsets_i(batch, task * 256 + t);
        SmemEdge* se = (SmemEdge*)sm;
        for (int i = t; i < Bb; i += NTHR) se->hist[i] = 0;
        __syncthreads();
        for (int task = eb; task < EDGT; task += EDGB)
            dev_edge_i(edge, batch, task * 256 + t, se->hist);
        __syncthreads();
        for (int b = t; b < Bb; b += NTHR) {
            int v = se->hist[b];
            if (v) atomicAdd(&g_nedges[b], v);
        }
    }
    gbar();

    // ---- phase 2: GEMM1 (512 tile tasks)
    if (bid < 512) {
        SmemGemm* sg = (SmemGemm*)sm;
        int z = bid >> 7, rem = bid & 127;
        dev_gemm1_task(W1, z, (rem & 15) * BN, (rem >> 4) * BM, sg);
    }
    gbar();

    // ---- phase 3: MLP tail (128 tasks)
    if (bid < Bb / RWS) {
        SmemMlp* sl = (SmemMlp*)sm;
        dev_mlp2_task(W1, b1, lng, lnb, W2, b2, W3, b3, bid * RWS, sl);
    }
    gbar();

    // ---- phase 4: gated fusion, REVERSE order to hit the pool-cached L2 tail first
    for (int chunk = FCHUNKS - 1 - bid; chunk >= 0; chunk -= GRID)
        dev_fuse_chunk(xg, xa, batch, out, chunk);
}

// ---------------- fallback kernels (multi-launch path) --------------------------
__global__ void k_zero() { g_nedges[threadIdx.x] = 0; }

__global__ void k_offsets(const int* __restrict__ batch) {
    dev_offsets_i(batch, blockIdx.x * blockDim.x + threadIdx.x);
}

__global__ void __launch_bounds__(256) k_edges(const int* __restrict__ ei,
                                               const int* __restrict__ batch) {
    __shared__ int hist[Bb];
    for (int i = threadIdx.x; i < Bb; i += 256) hist[i] = 0;
    __syncthreads();
    dev_edge_i(ei, batch, blockIdx.x * 256 + threadIdx.x, hist);
    __syncthreads();
    for (int b = threadIdx.x; b < Bb; b += 256) {
        int v = hist[b];
        if (v) atomicAdd(&g_nedges[b], v);
    }
}

__global__ void __launch_bounds__(256) k_pool(const float* __restrict__ xg,
                                              const float* __restrict__ xa,
                                              const int* __restrict__ batch) {
    __shared__ __align__(16) char sm[sizeof(SmemPool)];
    dev_pool_task(blockIdx.y ? xa : xg, batch, blockIdx.x, blockIdx.y, (SmemPool*)sm);
}

__global__ void __launch_bounds__(256) k_gemm1(const float* __restrict__ W1) {
    __shared__ __align__(16) char sm[sizeof(SmemGemm)];
    dev_gemm1_task(W1, blockIdx.z, blockIdx.x * BN, blockIdx.y * BM, (SmemGemm*)sm);
}

__global__ void __launch_bounds__(256) k_mlp2(
    const float* __restrict__ W1, const float* __restrict__ b1,
    const float* __restrict__ lng, const float* __restrict__ lnb,
    const float* __restrict__ W2, const float* __restrict__ b2,
    const float* __restrict__ W3, const float* __restrict__ b3) {
    __shared__ __align__(16) char sm[sizeof(SmemMlp)];
    dev_mlp2_task(W1, b1, lng, lnb, W2, b2, W3, b3, blockIdx.x * RWS, (SmemMlp*)sm);
}

__global__ void __launch_bounds__(256) k_fuse(const float* __restrict__ xg,
                                              const float* __restrict__ xa,
                                              const int* __restrict__ batch,
                                              float* __restrict__ out) {
    dev_fuse_chunk(xg, xa, batch, out, blockIdx.x);
}

// ---------------- launch --------------------------------------------------------
extern "C" void kernel_launch(void* const* d_in, const int* in_sizes, int n_in,
                              void* d_out, int out_size) {
    const float* x_ggnn  = (const float*)d_in[0];
    const float* x_appnp = (const float*)d_in[1];
    const int*   edge    = (const int*)d_in[2];
    const int*   batch   = (const int*)d_in[3];
    const float* W1 = (const float*)d_in[4];
    const float* b1 = (const float*)d_in[5];
    const float* lng = (const float*)d_in[6];
    const float* lnb = (const float*)d_in[7];
    const float* W2 = (const float*)d_in[8];
    const float* b2 = (const float*)d_in[9];
    const float* W3 = (const float*)d_in[10];
    const float* b3 = (const float*)d_in[11];
    float* out = (float*)d_out;

    // residency check: megakernel needs all GRID blocks co-resident
    int dev = 0, nsm = 0, occ = 0;
    cudaGetDevice(&dev);
    cudaDeviceGetAttribute(&nsm, cudaDevAttrMultiProcessorCount, dev);
    cudaOccupancyMaxActiveBlocksPerMultiprocessor(&occ, k_mega, NTHR, 0);

    if (occ * nsm >= GRID) {
        k_mega<<<GRID, NTHR>>>(x_ggnn, x_appnp, edge, batch,
                               W1, b1, lng, lnb, W2, b2, W3, b3, out);
    } else {
        // serial fallback (no grid barrier needed)
        k_zero<<<1, Bb>>>();
        k_offsets<<<(Nn + 255) / 256, 256>>>(batch);
        k_edges<<<EDGT, 256>>>(edge, batch);
        k_pool<<<dim3(Bb, 2), 256>>>(x_ggnn, x_appnp, batch);
        k_gemm1<<<dim3(Hh / BN, Bb / BM, NSPLIT), 256>>>(W1);
        k_mlp2<<<Bb / RWS, 256>>>(W1, b1, lng, lnb, W2, b2, W3, b3);
        k_fuse<<<FCHUNKS, 256>>>(x_ggnn, x_appnp, batch, out);
    }
}

// round 14
// speedup vs baseline: 1.1026x; 1.1026x over previous
#include <cuda_runtime.h>
#include <math.h>

#define Nn 100000
#define Ee 3200000
#define Hh 512
#define Bb 512
#define RWS 4
#define BM 64
#define BN 32
#define BK 32
#define KK 1024
#define KQ 256
#define NSPLIT 4
#define NCQ (KQ / BK)
#define GRID 592
#define NTHR 256
#define POOLB 512
#define EDGB (GRID - POOLB)        // 80 blocks for offsets+edges
#define OFFT ((Nn + 255) / 256)    // 391
#define EDGT (Ee / 4 / 256)        // 3125
#define FCHUNKS ((Nn * 128) / 512) // 25000

// ---------------- scratch ----------------
__device__ int   g_off[Bb + 1];
__device__ int   g_nedges[Bb];
__device__ float g_poolT[KK][Bb];
__device__ float g_pool[Bb][KK];
__device__ float g_hp[NSPLIT][Bb][Hh];
__device__ float g_w[Bb][2];
__device__ unsigned bar_cnt = 0;
__device__ volatile unsigned bar_gen = 0;

// ---------------- shared layouts ----------------
struct SmemGemm { float As[2][BK][BM]; float Ws[2][BK][BN]; };   // 24576 B
struct SmemPool { int bounds[2]; float4 sacc[128]; };
struct SmemEdge { int hist[Bb]; };
struct SmemMlp {
    float comp[RWS][4];
    float ts[RWS][Hh];
    float red[RWS][8];
    float red2[8][3];
    float sstat[RWS][3];
    float mu[RWS], rs[RWS];
    float red3[8][RWS][2];
    float raw[RWS][2];
};

// ---------------- grid barrier ----------------
__device__ __forceinline__ void gbar() {
    __threadfence();
    __syncthreads();
    if (threadIdx.x == 0) {
        unsigned g = bar_gen;
        if (atomicAdd(&bar_cnt, 1) == GRID - 1) {
            bar_cnt = 0;
            __threadfence();
            bar_gen = g + 1;
        } else {
            while (bar_gen == g) __nanosleep(64);
        }
    }
    __syncthreads();
}

// ---------------- device phase bodies ----------------
__device__ __forceinline__ int lbound(const int* __restrict__ batch, int key) {
    int lo = 0, hi = Nn;
    while (lo < hi) {
        int mid = (lo + hi) >> 1;
        if (batch[mid] < key) lo = mid + 1; else hi = mid;
    }
    return lo;
}

__device__ __forceinline__ void dev_pool_task(const float* __restrict__ x,
                                              const int* __restrict__ batch,
                                              int b, int half, SmemPool* sp) {
    int t = threadIdx.x, pr = t >> 7, c = t & 127;
    if (t == 0)   sp->bounds[0] = lbound(batch, b);
    if (t == 128) sp->bounds[1] = lbound(batch, b + 1);
    __syncthreads();
    int s0 = sp->bounds[0], e0 = sp->bounds[1];

    const float4* p = ((const float4*)x) + c;
    float4 acc = make_float4(0.f, 0.f, 0.f, 0.f);
    int r = s0 + pr;
    for (; r + 14 < e0; r += 16) {
        float4 v0 = __ldcs(&p[(size_t)(r +  0) * 128]);
        float4 v1 = __ldcs(&p[(size_t)(r +  2) * 128]);
        float4 v2 = __ldcs(&p[(size_t)(r +  4) * 128]);
        float4 v3 = __ldcs(&p[(size_t)(r +  6) * 128]);
        float4 v4 = __ldcs(&p[(size_t)(r +  8) * 128]);
        float4 v5 = __ldcs(&p[(size_t)(r + 10) * 128]);
        float4 v6 = __ldcs(&p[(size_t)(r + 12) * 128]);
        float4 v7 = __ldcs(&p[(size_t)(r + 14) * 128]);
        acc.x += (v0.x + v1.x) + (v2.x + v3.x) + ((v4.x + v5.x) + (v6.x + v7.x));
        acc.y += (v0.y + v1.y) + (v2.y + v3.y) + ((v4.y + v5.y) + (v6.y + v7.y));
        acc.z += (v0.z + v1.z) + (v2.z + v3.z) + ((v4.z + v5.z) + (v6.z + v7.z));
        acc.w += (v0.w + v1.w) + (v2.w + v3.w) + ((v4.w + v5.w) + (v6.w + v7.w));
    }
    for (; r < e0; r += 2) {
        float4 v = __ldcs(&p[(size_t)r * 128]);
        acc.x += v.x; acc.y += v.y; acc.z += v.z; acc.w += v.w;
    }

    if (pr == 1) sp->sacc[c] = acc;
    __syncthreads();
    if (pr == 0) {
        float4 o = sp->sacc[c];
        float inv = 1.f / fmaxf((float)(e0 - s0), 1.f);
        float4 m = make_float4((acc.x + o.x) * inv, (acc.y + o.y) * inv,
                               (acc.z + o.z) * inv, (acc.w + o.w) * inv);
        int kb = half * Hh + 4 * c;
        g_poolT[kb + 0][b] = m.x;
        g_poolT[kb + 1][b] = m.y;
        g_poolT[kb + 2][b] = m.z;
        g_poolT[kb + 3][b] = m.w;
        *(float4*)&g_pool[b][kb] = m;
    }
}

__device__ __forceinline__ void dev_offsets_i(const int* __restrict__ batch, int i) {
    if (i >= Nn) return;
    int c = batch[i];
    int p = (i == 0) ? -1 : batch[i - 1];
    for (int b = p + 1; b <= c; b++) g_off[b] = i;
    if (i == Nn - 1) {
        for (int b = c + 1; b <= Bb; b++) g_off[b] = Nn;
    }
}

__device__ __forceinline__ void dev_edge_i(const int* __restrict__ ei,
                                           const int* __restrict__ batch,
                                           int i, int* hist) {
    const int4* src4 = (const int4*)ei;
    const int4* dst4 = (const int4*)(ei + Ee);
    int4 s = __ldg(&src4[i]);
    int4 d = __ldg(&dst4[i]);
    int sg0 = __ldg(&batch[s.x]), sg1 = __ldg(&batch[s.y]);
    int sg2 = __ldg(&batch[s.z]), sg3 = __ldg(&batch[s.w]);
    int dg0 = __ldg(&batch[d.x]), dg1 = __ldg(&batch[d.y]);
    int dg2 = __ldg(&batch[d.z]), dg3 = __ldg(&batch[d.w]);
    if (sg0 == dg0) atomicAdd(&hist[sg0], 1);
    if (sg1 == dg1) atomicAdd(&hist[sg1], 1);
    if (sg2 == dg2) atomicAdd(&hist[sg2], 1);
    if (sg3 == dg3) atomicAdd(&hist[sg3], 1);
}

__device__ __forceinline__ void dev_gemm1_task(const float* __restrict__ W1,
                                               int z, int n0, int m0, SmemGemm* sg) {
    int t = threadIdx.x;
    int tn = t & 15;
    int tm = t >> 4;
    int ak = t >> 4;
    int af = t & 15;
    int wk = t >> 3;
    int wq = t & 7;

    const float* Abase = &g_poolT[z * KQ][0];
    const float* Wbase = W1 + (size_t)z * KQ * Hh;
    size_t aIdx0 = (size_t)ak * Bb + m0 + 4 * af;
    size_t aIdx1 = (size_t)(ak + 16) * Bb + m0 + 4 * af;
    size_t wIdx  = (size_t)wk * Hh + n0 + 4 * wq;

    *(float4*)&sg->As[0][ak][4 * af]      = *(const float4*)&Abase[aIdx0];
    *(float4*)&sg->As[0][ak + 16][4 * af] = *(const float4*)&Abase[aIdx1];
    *(float4*)&sg->Ws[0][wk][4 * wq]      = *(const float4*)&Wbase[wIdx];
    __syncthreads();

    float acc[4][2];
    #pragma unroll
    for (int j = 0; j < 4; j++) { acc[j][0] = 0.f; acc[j][1] = 0.f; }

    for (int c = 0; c < NCQ; c++) {
        int nb = c & 1;
        float4 ra0, ra1, rw;
        if (c + 1 < NCQ) {
            size_t koff  = (size_t)(c + 1) * BK * Bb;
            size_t kwoff = (size_t)(c + 1) * BK * Hh;
            ra0 = *(const float4*)&Abase[koff + aIdx0];
            ra1 = *(const float4*)&Abase[koff + aIdx1];
            rw  = *(const float4*)&Wbase[kwoff + wIdx];
        }
        #pragma unroll
        for (int k = 0; k < BK; k++) {
            float4 a = *(float4*)&sg->As[nb][k][4 * tm];
            float2 w = *(float2*)&sg->Ws[nb][k][2 * tn];
            acc[0][0] += a.x * w.x; acc[0][1] += a.x * w.y;
            acc[1][0] += a.y * w.x; acc[1][1] += a.y * w.y;
            acc[2][0] += a.z * w.x; acc[2][1] += a.z * w.y;
            acc[3][0] += a.w * w.x; acc[3][1] += a.w * w.y;
        }
        if (c + 1 < NCQ) {
            __syncthreads();
            *(float4*)&sg->As[1 - nb][ak][4 * af]      = ra0;
            *(float4*)&sg->As[1 - nb][ak + 16][4 * af] = ra1;
            *(float4*)&sg->Ws[1 - nb][wk][4 * wq]      = rw;
            __syncthreads();
        }
    }

    #pragma unroll
    for (int j = 0; j < 4; j++) {
        *(float2*)&g_hp[z][m0 + 4 * tm + j][n0 + 2 * tn] = make_float2(acc[j][0], acc[j][1]);
    }
}

__device__ __forceinline__ void dev_mlp2_task(
    const float* __restrict__ W1, const float* __restrict__ b1,
    const float* __restrict__ lng, const float* __restrict__ lnb,
    const float* __restrict__ W2, const float* __restrict__ b2,
    const float* __restrict__ W3, const float* __restrict__ b3,
    int row0, SmemMlp* sl)
{
    int t = threadIdx.x;
    int lane = t & 31, wid = t >> 5;

    #pragma unroll
    for (int r = 0; r < RWS; r++) {
        int b = row0 + r;
        float2 gg = *(const float2*)&g_pool[b][2 * t];
        float2 aa = *(const float2*)&g_pool[b][Hh + 2 * t];
        float dot = gg.x * aa.x + gg.y * aa.y;
        float n2g = gg.x * gg.x + gg.y * gg.y;
        float n2a = aa.x * aa.x + aa.y * aa.y;
        #pragma unroll
        for (int o = 16; o > 0; o >>= 1) {
            dot += __shfl_down_sync(0xFFFFFFFFu, dot, o);
            n2g += __shfl_down_sync(0xFFFFFFFFu, n2g, o);
            n2a += __shfl_down_sync(0xFFFFFFFFu, n2a, o);
        }
        if (lane == 0) { sl->red2[wid][0] = dot; sl->red2[wid][1] = n2g; sl->red2[wid][2] = n2a; }
        __syncthreads();
        if (t < 3) {
            float s = 0.f;
            #pragma unroll
            for (int w = 0; w < 8; w++) s += sl->red2[w][t];
            sl->sstat[r][t] = s;
        }
        __syncthreads();
    }

    if (t < RWS) {
        int b = row0 + t;
        float cnt = (float)(g_off[b + 1] - g_off[b]);
        float ne  = (float)g_nedges[b];
        g_nedges[b] = 0;   // consume-and-reset for next replay
        float scale   = logf(cnt + 1.f) * (1.f / logf(501.0f));
        float density = ne / (cnt * (cnt - 1.f) + 1e-8f);
        float avgdeg  = ne / (cnt + 1e-8f);
        float avn     = fminf(avgdeg * 0.1f, 1.f);
        float dot = sl->sstat[t][0], n2g = sl->sstat[t][1], n2a = sl->sstat[t][2];
        float na = fmaxf(sqrtf(n2g), 1e-8f);
        float nb = fmaxf(sqrtf(n2a), 1e-8f);
        float cosv = dot / (na * nb);
        sl->comp[t][0] = scale;
        sl->comp[t][1] = density;
        sl->comp[t][2] = avn;
        sl->comp[t][3] = (1.f - cosv) * 0.5f;
    }
    __syncthreads();

    float2 w1t[4];
    #pragma unroll
    for (int j = 0; j < 4; j++)
        w1t[j] = *(const float2*)&W1[(size_t)(KK + j) * Hh + 2 * t];
    float2 bb = ((const float2*)b1)[t];
    float2 h[RWS];
    #pragma unroll
    for (int r = 0; r < RWS; r++) {
        float2 hg0 = *(const float2*)&g_hp[0][row0 + r][2 * t];
        float2 hg1 = *(const float2*)&g_hp[1][row0 + r][2 * t];
        float2 hg2 = *(const float2*)&g_hp[2][row0 + r][2 * t];
        float2 hg3 = *(const float2*)&g_hp[3][row0 + r][2 * t];
        float hx = (hg0.x + hg1.x) + (hg2.x + hg3.x) + bb.x;
        float hy = (hg0.y + hg1.y) + (hg2.y + hg3.y) + bb.y;
        #pragma unroll
        for (int j = 0; j < 4; j++) {
            hx += sl->comp[r][j] * w1t[j].x;
            hy += sl->comp[r][j] * w1t[j].y;
        }
        h[r] = make_float2(hx, hy);
    }

    #pragma unroll
    for (int r = 0; r < RWS; r++) {
        float p = h[r].x + h[r].y;
        #pragma unroll
        for (int o = 16; o > 0; o >>= 1) p += __shfl_down_sync(0xFFFFFFFFu, p, o);
        if (lane == 0) sl->red[r][wid] = p;
    }
    __syncthreads();
    if (t < RWS) {
        float s = 0.f;
        #pragma unroll
        for (int w = 0; w < 8; w++) s += sl->red[t][w];
        sl->mu[t] = s * (1.f / (float)Hh);
    }
    __syncthreads();
    #pragma unroll
    for (int r = 0; r < RWS; r++) {
        float dx = h[r].x - sl->mu[r], dy = h[r].y - sl->mu[r];
        float p = dx * dx + dy * dy;
        #pragma unroll
        for (int o = 16; o > 0; o >>= 1) p += __shfl_down_sync(0xFFFFFFFFu, p, o);
        if (lane == 0) sl->red[r][wid] = p;
    }
    __syncthreads();
    if (t < RWS) {
        float s = 0.f;
        #pragma unroll
        for (int w = 0; w < 8; w++) s += sl->red[t][w];
        sl->rs[t] = rsqrtf(s * (1.f / (float)Hh) + 1e-5f);
    }
    __syncthreads();
    {
        float2 gv = ((const float2*)lng)[t];
        float2 bv = ((const float2*)lnb)[t];
        #pragma unroll
        for (int r = 0; r < RWS; r++) {
            float vx = (h[r].x - sl->mu[r]) * sl->rs[r] * gv.x + bv.x;
            float vy = (h[r].y - sl->mu[r]) * sl->rs[r] * gv.y + bv.y;
            sl->ts[r][2 * t]     = fmaxf(vx, 0.f);
            sl->ts[r][2 * t + 1] = fmaxf(vy, 0.f);
        }
    }
    __syncthreads();

    float u[RWS];
    #pragma unroll
    for (int r = 0; r < RWS; r++) u[r] = 0.f;
    float wr[4];
    #pragma unroll
    for (int j = 0; j < 4; j++) wr[j] = W2[(size_t)j * 256 + t];
    for (int k = 0; k < Hh; k += 4) {
        float wn[4];
        if (k + 4 < Hh) {
            #pragma unroll
            for (int j = 0; j < 4; j++) wn[j] = W2[(size_t)(k + 4 + j) * 256 + t];
        }
        float ta[RWS][4];
        #pragma unroll
        for (int r = 0; r < RWS; r++) {
            float4 q = *(const float4*)&sl->ts[r][k];
            ta[r][0] = q.x; ta[r][1] = q.y; ta[r][2] = q.z; ta[r][3] = q.w;
        }
        #pragma unroll
        for (int kk = 0; kk < 4; kk++) {
            #pragma unroll
            for (int r = 0; r < RWS; r++) u[r] += ta[r][kk] * wr[kk];
        }
        #pragma unroll
        for (int j = 0; j < 4; j++) wr[j] = wn[j];
    }
    float bt = b2[t];
    #pragma unroll
    for (int r = 0; r < RWS; r++) u[r] = fmaxf(u[r] + bt, 0.f);

    float w30 = W3[2 * t], w31 = W3[2 * t + 1];
    float p0[RWS], p1[RWS];
    #pragma unroll
    for (int r = 0; r < RWS; r++) { p0[r] = u[r] * w30; p1[r] = u[r] * w31; }
    #pragma unroll
    for (int o = 16; o > 0; o >>= 1) {
        #pragma unroll
        for (int r = 0; r < RWS; r++) {
            p0[r] += __shfl_down_sync(0xFFFFFFFFu, p0[r], o);
            p1[r] += __shfl_down_sync(0xFFFFFFFFu, p1[r], o);
        }
    }
    if (lane == 0) {
        #pragma unroll
        for (int r = 0; r < RWS; r++) { sl->red3[wid][r][0] = p0[r]; sl->red3[wid][r][1] = p1[r]; }
    }
    __syncthreads();
    if (t < RWS * 2) {
        int r = t >> 1, c = t & 1;
        float s = 0.f;
        #pragma unroll
        for (int w = 0; w < 8; w++) s += sl->red3[w][r][c];
        sl->raw[r][c] = s + b3[c];
    }
    __syncthreads();
    if (t < RWS) {
        float r0 = sl->raw[t][0], r1 = sl->raw[t][1];
        float m = fmaxf(r0, r1);
        float e0 = expf(r0 - m), e1 = expf(r1 - m);
        float inv = 1.f / (e0 + e1);
        g_w[row0 + t][0] = e0 * inv;
        g_w[row0 + t][1] = e1 * inv;
    }
}

__device__ __forceinline__ void dev_fuse_chunk(const float* __restrict__ xg,
                                               const float* __restrict__ xa,
                                               const int* __restrict__ batch,
                                               float* __restrict__ out, int chunk) {
    size_t i0 = (size_t)chunk * 512 + threadIdx.x;
    size_t i1 = i0 + 256;
    int n0 = (int)(i0 >> 7);
    int n1 = (int)(i1 >> 7);
    int b0 = __ldg(&batch[n0]);
    int b1 = __ldg(&batch[n1]);
    float4 g0 = __ldcs(((const float4*)xg) + i0);
    float4 a0 = __ldcs(((const float4*)xa) + i0);
    float4 g1 = __ldcs(((const float4*)xg) + i1);
    float4 a1 = __ldcs(((const float4*)xa) + i1);
    float w00 = g_w[b0][0], w01 = g_w[b0][1];
    float w10 = g_w[b1][0], w11 = g_w[b1][1];
    float4 o0, o1;
    o0.x = w00 * g0.x + w01 * a0.x;
    o0.y = w00 * g0.y + w01 * a0.y;
    o0.z = w00 * g0.z + w01 * a0.z;
    o0.w = w00 * g0.w + w01 * a0.w;
    o1.x = w10 * g1.x + w11 * a1.x;
    o1.y = w10 * g1.y + w11 * a1.y;
    o1.z = w10 * g1.z + w11 * a1.z;
    o1.w = w10 * g1.w + w11 * a1.w;
    __stcs(((float4*)out) + i0, o0);
    __stcs(((float4*)out) + i1, o1);
}

// ---------------- persistent kernel: phases 1-3 only ----------------
__global__ void __launch_bounds__(NTHR, 4) k_mega1(
    const float* __restrict__ xg, const float* __restrict__ xa,
    const int* __restrict__ edge, const int* __restrict__ batch,
    const float* __restrict__ W1, const float* __restrict__ b1,
    const float* __restrict__ lng, const float* __restrict__ lnb,
    const float* __restrict__ W2, const float* __restrict__ b2,
    const float* __restrict__ W3, const float* __restrict__ b3)
{
    __shared__ __align__(16) char sm[sizeof(SmemGemm)];
    int bid = blockIdx.x;
    int t = threadIdx.x;

    // ---- phase 1: pool (blocks 0..511) || offsets+edges (blocks 512..591)
    if (bid < POOLB) {
        SmemPool* sp = (SmemPool*)sm;
        dev_pool_task(xg, batch, bid, 0, sp);
        __syncthreads();
        dev_pool_task(xa, batch, bid, 1, sp);
    } else {
        int eb = bid - POOLB;
        for (int task = eb; task < OFFT; task += EDGB)
            dev_offsets_i(batch, task * 256 + t);
        SmemEdge* se = (SmemEdge*)sm;
        for (int i = t; i < Bb; i += NTHR) se->hist[i] = 0;
        __syncthreads();
        for (int task = eb; task < EDGT; task += EDGB)
            dev_edge_i(edge, batch, task * 256 + t, se->hist);
        __syncthreads();
        for (int b = t; b < Bb; b += NTHR) {
            int v = se->hist[b];
            if (v) atomicAdd(&g_nedges[b], v);
        }
    }
    gbar();

    // ---- phase 2: GEMM1 (512 tile tasks)
    if (bid < 512) {
        SmemGemm* sg = (SmemGemm*)sm;
        int z = bid >> 7, rem = bid & 127;
        dev_gemm1_task(W1, z, (rem & 15) * BN, (rem >> 4) * BM, sg);
    }
    gbar();

    // ---- phase 3: MLP tail (128 tasks); kernel end = implicit sync for fuse
    if (bid < Bb / RWS) {
        SmemMlp* sl = (SmemMlp*)sm;
        dev_mlp2_task(W1, b1, lng, lnb, W2, b2, W3, b3, bid * RWS, sl);
    }
}

// ---------------- standalone high-occupancy fuse --------------------------------
__global__ void __launch_bounds__(256) k_fuse(const float* __restrict__ xg,
                                              const float* __restrict__ xa,
                                              const int* __restrict__ batch,
                                              float* __restrict__ out) {
    dev_fuse_chunk(xg, xa, batch, out, blockIdx.x);
}

// ---------------- fallback kernels (multi-launch path) --------------------------
__global__ void k_zero() { g_nedges[threadIdx.x] = 0; }

__global__ void k_offsets(const int* __restrict__ batch) {
    dev_offsets_i(batch, blockIdx.x * blockDim.x + threadIdx.x);
}

__global__ void __launch_bounds__(256) k_edges(const int* __restrict__ ei,
                                               const int* __restrict__ batch) {
    __shared__ int hist[Bb];
    for (int i = threadIdx.x; i < Bb; i += 256) hist[i] = 0;
    __syncthreads();
    dev_edge_i(ei, batch, blockIdx.x * 256 + threadIdx.x, hist);
    __syncthreads();
    for (int b = threadIdx.x; b < Bb; b += 256) {
        int v = hist[b];
        if (v) atomicAdd(&g_nedges[b], v);
    }
}

__global__ void __launch_bounds__(256) k_pool(const float* __restrict__ xg,
                                              const float* __restrict__ xa,
                                              const int* __restrict__ batch) {
    __shared__ __align__(16) char sm[sizeof(SmemPool)];
    dev_pool_task(blockIdx.y ? xa : xg, batch, blockIdx.x, blockIdx.y, (SmemPool*)sm);
}

__global__ void __launch_bounds__(256) k_gemm1(const float* __restrict__ W1) {
    __shared__ __align__(16) char sm[sizeof(SmemGemm)];
    dev_gemm1_task(W1, blockIdx.z, blockIdx.x * BN, blockIdx.y * BM, (SmemGemm*)sm);
}

__global__ void __launch_bounds__(256) k_mlp2(
    const float* __restrict__ W1, const float* __restrict__ b1,
    const float* __restrict__ lng, const float* __restrict__ lnb,
    const float* __restrict__ W2, const float* __restrict__ b2,
    const float* __restrict__ W3, const float* __restrict__ b3) {
    __shared__ __align__(16) char sm[sizeof(SmemMlp)];
    dev_mlp2_task(W1, b1, lng, lnb, W2, b2, W3, b3, blockIdx.x * RWS, (SmemMlp*)sm);
}

// ---------------- launch --------------------------------------------------------
extern "C" void kernel_launch(void* const* d_in, const int* in_sizes, int n_in,
                              void* d_out, int out_size) {
    const float* x_ggnn  = (const float*)d_in[0];
    const float* x_appnp = (const float*)d_in[1];
    const int*   edge    = (const int*)d_in[2];
    const int*   batch   = (const int*)d_in[3];
    const float* W1 = (const float*)d_in[4];
    const float* b1 = (const float*)d_in[5];
    const float* lng = (const float*)d_in[6];
    const float* lnb = (const float*)d_in[7];
    const float* W2 = (const float*)d_in[8];
    const float* b2 = (const float*)d_in[9];
    const float* W3 = (const float*)d_in[10];
    const float* b3 = (const float*)d_in[11];
    float* out = (float*)d_out;

    // residency check: persistent kernel needs all GRID blocks co-resident
    int dev = 0, nsm = 0, occ = 0;
    cudaGetDevice(&dev);
    cudaDeviceGetAttribute(&nsm, cudaDevAttrMultiProcessorCount, dev);
    cudaOccupancyMaxActiveBlocksPerMultiprocessor(&occ, k_mega1, NTHR, 0);

    if (occ * nsm >= GRID) {
        k_mega1<<<GRID, NTHR>>>(x_ggnn, x_appnp, edge, batch,
                                W1, b1, lng, lnb, W2, b2, W3, b3);
        k_fuse<<<FCHUNKS, 256>>>(x_ggnn, x_appnp, batch, out);
    } else {
        // serial fallback (no grid barrier needed)
        k_zero<<<1, Bb>>>();
        k_offsets<<<(Nn + 255) / 256, 256>>>(batch);
        k_edges<<<EDGT, 256>>>(edge, batch);
        k_pool<<<dim3(Bb, 2), 256>>>(x_ggnn, x_appnp, batch);
        k_gemm1<<<dim3(Hh / BN, Bb / BM, NSPLIT), 256>>>(W1);
        k_mlp2<<<Bb / RWS, 256>>>(W1, b1, lng, lnb, W2, b2, W3, b3);
        k_fuse<<<FCHUNKS, 256>>>(x_ggnn, x_appnp, batch, out);
    }
}

// round 15
// speedup vs baseline: 1.1337x; 1.0282x over previous
#include <cuda_runtime.h>
#include <math.h>

#define Nn 100000
#define Ee 3200000
#define Hh 512
#define Bb 512
#define RWS 4
#define BM 64
#define BN 32
#define BK 32
#define KK 1024
#define KQ 256
#define NSPLIT 4
#define NCQ (KQ / BK)
#define NTHR 256
#define P1EDGE 80                    // edge/offset blocks in phase 1
#define P1GRID (P1EDGE + 2 * Bb)     // 80 + 1024 = 1104
#define GRID2 512                    // persistent phase-2 grid
#define OFFT ((Nn + 255) / 256)      // 391
#define EDGT (Ee / 4 / 256)          // 3125
#define FCHUNKS ((Nn * 128) / 512)   // 25000

// ---------------- scratch ----------------
__device__ int   g_off[Bb + 1];
__device__ int   g_nedges[Bb];
__device__ float g_poolT[KK][Bb];
__device__ float g_pool[Bb][KK];
__device__ float g_hp[NSPLIT][Bb][Hh];
__device__ float g_w[Bb][2];
__device__ unsigned bar_cnt = 0;
__device__ volatile unsigned bar_gen = 0;

// ---------------- shared layouts ----------------
struct SmemGemm { float As[2][BK][BM]; float Ws[2][BK][BN]; };   // 24576 B
struct SmemPool { int bounds[2]; float4 sacc[128]; };
struct SmemEdge { int hist[Bb]; };
struct SmemMlp {
    float comp[RWS][4];
    float ts[RWS][Hh];
    float red[RWS][8];
    float red2[8][3];
    float sstat[RWS][3];
    float mu[RWS], rs[RWS];
    float red3[8][RWS][2];
    float raw[RWS][2];
};

// ---------------- grid barrier (count = n blocks) ----------------
__device__ __forceinline__ void gbarN(unsigned n) {
    __threadfence();
    __syncthreads();
    if (threadIdx.x == 0) {
        unsigned g = bar_gen;
        if (atomicAdd(&bar_cnt, 1) == n - 1) {
            bar_cnt = 0;
            __threadfence();
            bar_gen = g + 1;
        } else {
            while (bar_gen == g) __nanosleep(64);
        }
    }
    __syncthreads();
}

// ---------------- device bodies ----------------
__device__ __forceinline__ int lbound(const int* __restrict__ batch, int key) {
    int lo = 0, hi = Nn;
    while (lo < hi) {
        int mid = (lo + hi) >> 1;
        if (batch[mid] < key) lo = mid + 1; else hi = mid;
    }
    return lo;
}

// R5-proven pool body: one (graph, array) task, 4-deep stride-2 parity unroll
__device__ __forceinline__ void dev_pool_task(const float* __restrict__ x,
                                              const int* __restrict__ batch,
                                              int b, int half, SmemPool* sp) {
    int t = threadIdx.x, pr = t >> 7, c = t & 127;
    if (t == 0)   sp->bounds[0] = lbound(batch, b);
    if (t == 128) sp->bounds[1] = lbound(batch, b + 1);
    __syncthreads();
    int s0 = sp->bounds[0], e0 = sp->bounds[1];

    const float4* p = ((const float4*)x) + c;
    float4 acc = make_float4(0.f, 0.f, 0.f, 0.f);
    int r = s0 + pr;
    for (; r + 6 < e0; r += 8) {
        float4 v0 = __ldcs(&p[(size_t)(r + 0) * 128]);
        float4 v1 = __ldcs(&p[(size_t)(r + 2) * 128]);
        float4 v2 = __ldcs(&p[(size_t)(r + 4) * 128]);
        float4 v3 = __ldcs(&p[(size_t)(r + 6) * 128]);
        acc.x += v0.x + v1.x + v2.x + v3.x;
        acc.y += v0.y + v1.y + v2.y + v3.y;
        acc.z += v0.z + v1.z + v2.z + v3.z;
        acc.w += v0.w + v1.w + v2.w + v3.w;
    }
    for (; r < e0; r += 2) {
        float4 v = __ldcs(&p[(size_t)r * 128]);
        acc.x += v.x; acc.y += v.y; acc.z += v.z; acc.w += v.w;
    }

    if (pr == 1) sp->sacc[c] = acc;
    __syncthreads();
    if (pr == 0) {
        float4 o = sp->sacc[c];
        float inv = 1.f / fmaxf((float)(e0 - s0), 1.f);
        float4 m = make_float4((acc.x + o.x) * inv, (acc.y + o.y) * inv,
                               (acc.z + o.z) * inv, (acc.w + o.w) * inv);
        int kb = half * Hh + 4 * c;
        g_poolT[kb + 0][b] = m.x;
        g_poolT[kb + 1][b] = m.y;
        g_poolT[kb + 2][b] = m.z;
        g_poolT[kb + 3][b] = m.w;
        *(float4*)&g_pool[b][kb] = m;
    }
}

__device__ __forceinline__ void dev_offsets_i(const int* __restrict__ batch, int i) {
    if (i >= Nn) return;
    int c = batch[i];
    int p = (i == 0) ? -1 : batch[i - 1];
    for (int b = p + 1; b <= c; b++) g_off[b] = i;
    if (i == Nn - 1) {
        for (int b = c + 1; b <= Bb; b++) g_off[b] = Nn;
    }
}

__device__ __forceinline__ void dev_edge_i(const int* __restrict__ ei,
                                           const int* __restrict__ batch,
                                           int i, int* hist) {
    const int4* src4 = (const int4*)ei;
    const int4* dst4 = (const int4*)(ei + Ee);
    int4 s = __ldg(&src4[i]);
    int4 d = __ldg(&dst4[i]);
    int sg0 = __ldg(&batch[s.x]), sg1 = __ldg(&batch[s.y]);
    int sg2 = __ldg(&batch[s.z]), sg3 = __ldg(&batch[s.w]);
    int dg0 = __ldg(&batch[d.x]), dg1 = __ldg(&batch[d.y]);
    int dg2 = __ldg(&batch[d.z]), dg3 = __ldg(&batch[d.w]);
    if (sg0 == dg0) atomicAdd(&hist[sg0], 1);
    if (sg1 == dg1) atomicAdd(&hist[sg1], 1);
    if (sg2 == dg2) atomicAdd(&hist[sg2], 1);
    if (sg3 == dg3) atomicAdd(&hist[sg3], 1);
}

__device__ __forceinline__ void dev_gemm1_task(const float* __restrict__ W1,
                                               int z, int n0, int m0, SmemGemm* sg) {
    int t = threadIdx.x;
    int tn = t & 15;
    int tm = t >> 4;
    int ak = t >> 4;
    int af = t & 15;
    int wk = t >> 3;
    int wq = t & 7;

    const float* Abase = &g_poolT[z * KQ][0];
    const float* Wbase = W1 + (size_t)z * KQ * Hh;
    size_t aIdx0 = (size_t)ak * Bb + m0 + 4 * af;
    size_t aIdx1 = (size_t)(ak + 16) * Bb + m0 + 4 * af;
    size_t wIdx  = (size_t)wk * Hh + n0 + 4 * wq;

    *(float4*)&sg->As[0][ak][4 * af]      = *(const float4*)&Abase[aIdx0];
    *(float4*)&sg->As[0][ak + 16][4 * af] = *(const float4*)&Abase[aIdx1];
    *(float4*)&sg->Ws[0][wk][4 * wq]      = *(const float4*)&Wbase[wIdx];
    __syncthreads();

    float acc[4][2];
    #pragma unroll
    for (int j = 0; j < 4; j++) { acc[j][0] = 0.f; acc[j][1] = 0.f; }

    for (int c = 0; c < NCQ; c++) {
        int nb = c & 1;
        float4 ra0, ra1, rw;
        if (c + 1 < NCQ) {
            size_t koff  = (size_t)(c + 1) * BK * Bb;
            size_t kwoff = (size_t)(c + 1) * BK * Hh;
            ra0 = *(const float4*)&Abase[koff + aIdx0];
            ra1 = *(const float4*)&Abase[koff + aIdx1];
            rw  = *(const float4*)&Wbase[kwoff + wIdx];
        }
        #pragma unroll
        for (int k = 0; k < BK; k++) {
            float4 a = *(float4*)&sg->As[nb][k][4 * tm];
            float2 w = *(float2*)&sg->Ws[nb][k][2 * tn];
            acc[0][0] += a.x * w.x; acc[0][1] += a.x * w.y;
            acc[1][0] += a.y * w.x; acc[1][1] += a.y * w.y;
            acc[2][0] += a.z * w.x; acc[2][1] += a.z * w.y;
            acc[3][0] += a.w * w.x; acc[3][1] += a.w * w.y;
        }
        if (c + 1 < NCQ) {
            __syncthreads();
            *(float4*)&sg->As[1 - nb][ak][4 * af]      = ra0;
            *(float4*)&sg->As[1 - nb][ak + 16][4 * af] = ra1;
            *(float4*)&sg->Ws[1 - nb][wk][4 * wq]      = rw;
            __syncthreads();
        }
    }

    #pragma unroll
    for (int j = 0; j < 4; j++) {
        *(float2*)&g_hp[z][m0 + 4 * tm + j][n0 + 2 * tn] = make_float2(acc[j][0], acc[j][1]);
    }
}

__device__ __forceinline__ void dev_mlp2_task(
    const float* __restrict__ W1, const float* __restrict__ b1,
    const float* __restrict__ lng, const float* __restrict__ lnb,
    const float* __restrict__ W2, const float* __restrict__ b2,
    const float* __restrict__ W3, const float* __restrict__ b3,
    int row0, SmemMlp* sl)
{
    int t = threadIdx.x;
    int lane = t & 31, wid = t >> 5;

    #pragma unroll
    for (int r = 0; r < RWS; r++) {
        int b = row0 + r;
        float2 gg = *(const float2*)&g_pool[b][2 * t];
        float2 aa = *(const float2*)&g_pool[b][Hh + 2 * t];
        float dot = gg.x * aa.x + gg.y * aa.y;
        float n2g = gg.x * gg.x + gg.y * gg.y;
        float n2a = aa.x * aa.x + aa.y * aa.y;
        #pragma unroll
        for (int o = 16; o > 0; o >>= 1) {
            dot += __shfl_down_sync(0xFFFFFFFFu, dot, o);
            n2g += __shfl_down_sync(0xFFFFFFFFu, n2g, o);
            n2a += __shfl_down_sync(0xFFFFFFFFu, n2a, o);
        }
        if (lane == 0) { sl->red2[wid][0] = dot; sl->red2[wid][1] = n2g; sl->red2[wid][2] = n2a; }
        __syncthreads();
        if (t < 3) {
            float s = 0.f;
            #pragma unroll
            for (int w = 0; w < 8; w++) s += sl->red2[w][t];
            sl->sstat[r][t] = s;
        }
        __syncthreads();
    }

    if (t < RWS) {
        int b = row0 + t;
        float cnt = (float)(g_off[b + 1] - g_off[b]);
        float ne  = (float)g_nedges[b];
        g_nedges[b] = 0;   // consume-and-reset for next replay
        float scale   = logf(cnt + 1.f) * (1.f / logf(501.0f));
        float density = ne / (cnt * (cnt - 1.f) + 1e-8f);
        float avgdeg  = ne / (cnt + 1e-8f);
        float avn     = fminf(avgdeg * 0.1f, 1.f);
        float dot = sl->sstat[t][0], n2g = sl->sstat[t][1], n2a = sl->sstat[t][2];
        float na = fmaxf(sqrtf(n2g), 1e-8f);
        float nb = fmaxf(sqrtf(n2a), 1e-8f);
        float cosv = dot / (na * nb);
        sl->comp[t][0] = scale;
        sl->comp[t][1] = density;
        sl->comp[t][2] = avn;
        sl->comp[t][3] = (1.f - cosv) * 0.5f;
    }
    __syncthreads();

    float2 w1t[4];
    #pragma unroll
    for (int j = 0; j < 4; j++)
        w1t[j] = *(const float2*)&W1[(size_t)(KK + j) * Hh + 2 * t];
    float2 bb = ((const float2*)b1)[t];
    float2 h[RWS];
    #pragma unroll
    for (int r = 0; r < RWS; r++) {
        float2 hg0 = *(const float2*)&g_hp[0][row0 + r][2 * t];
        float2 hg1 = *(const float2*)&g_hp[1][row0 + r][2 * t];
        float2 hg2 = *(const float2*)&g_hp[2][row0 + r][2 * t];
        float2 hg3 = *(const float2*)&g_hp[3][row0 + r][2 * t];
        float hx = (hg0.x + hg1.x) + (hg2.x + hg3.x) + bb.x;
        float hy = (hg0.y + hg1.y) + (hg2.y + hg3.y) + bb.y;
        #pragma unroll
        for (int j = 0; j < 4; j++) {
            hx += sl->comp[r][j] * w1t[j].x;
            hy += sl->comp[r][j] * w1t[j].y;
        }
        h[r] = make_float2(hx, hy);
    }

    #pragma unroll
    for (int r = 0; r < RWS; r++) {
        float p = h[r].x + h[r].y;
        #pragma unroll
        for (int o = 16; o > 0; o >>= 1) p += __shfl_down_sync(0xFFFFFFFFu, p, o);
        if (lane == 0) sl->red[r][wid] = p;
    }
    __syncthreads();
    if (t < RWS) {
        float s = 0.f;
        #pragma unroll
        for (int w = 0; w < 8; w++) s += sl->red[t][w];
        sl->mu[t] = s * (1.f / (float)Hh);
    }
    __syncthreads();
    #pragma unroll
    for (int r = 0; r < RWS; r++) {
        float dx = h[r].x - sl->mu[r], dy = h[r].y - sl->mu[r];
        float p = dx * dx + dy * dy;
        #pragma unroll
        for (int o = 16; o > 0; o >>= 1) p += __shfl_down_sync(0xFFFFFFFFu, p, o);
        if (lane == 0) sl->red[r][wid] = p;
    }
    __syncthreads();
    if (t < RWS) {
        float s = 0.f;
        #pragma unroll
        for (int w = 0; w < 8; w++) s += sl->red[t][w];
        sl->rs[t] = rsqrtf(s * (1.f / (float)Hh) + 1e-5f);
    }
    __syncthreads();
    {
        float2 gv = ((const float2*)lng)[t];
        float2 bv = ((const float2*)lnb)[t];
        #pragma unroll
        for (int r = 0; r < RWS; r++) {
            float vx = (h[r].x - sl->mu[r]) * sl->rs[r] * gv.x + bv.x;
            float vy = (h[r].y - sl->mu[r]) * sl->rs[r] * gv.y + bv.y;
            sl->ts[r][2 * t]     = fmaxf(vx, 0.f);
            sl->ts[r][2 * t + 1] = fmaxf(vy, 0.f);
        }
    }
    __syncthreads();

    float u[RWS];
    #pragma unroll
    for (int r = 0; r < RWS; r++) u[r] = 0.f;
    float wr[4];
    #pragma unroll
    for (int j = 0; j < 4; j++) wr[j] = W2[(size_t)j * 256 + t];
    for (int k = 0; k < Hh; k += 4) {
        float wn[4];
        if (k + 4 < Hh) {
            #pragma unroll
            for (int j = 0; j < 4; j++) wn[j] = W2[(size_t)(k + 4 + j) * 256 + t];
        }
        float ta[RWS][4];
        #pragma unroll
        for (int r = 0; r < RWS; r++) {
            float4 q = *(const float4*)&sl->ts[r][k];
            ta[r][0] = q.x; ta[r][1] = q.y; ta[r][2] = q.z; ta[r][3] = q.w;
        }
        #pragma unroll
        for (int kk = 0; kk < 4; kk++) {
            #pragma unroll
            for (int r = 0; r < RWS; r++) u[r] += ta[r][kk] * wr[kk];
        }
        #pragma unroll
        for (int j = 0; j < 4; j++) wr[j] = wn[j];
    }
    float bt = b2[t];
    #pragma unroll
    for (int r = 0; r < RWS; r++) u[r] = fmaxf(u[r] + bt, 0.f);

    float w30 = W3[2 * t], w31 = W3[2 * t + 1];
    float p0[RWS], p1[RWS];
    #pragma unroll
    for (int r = 0; r < RWS; r++) { p0[r] = u[r] * w30; p1[r] = u[r] * w31; }
    #pragma unroll
    for (int o = 16; o > 0; o >>= 1) {
        #pragma unroll
        for (int r = 0; r < RWS; r++) {
            p0[r] += __shfl_down_sync(0xFFFFFFFFu, p0[r], o);
            p1[r] += __shfl_down_sync(0xFFFFFFFFu, p1[r], o);
        }
    }
    if (lane == 0) {
        #pragma unroll
        for (int r = 0; r < RWS; r++) { sl->red3[wid][r][0] = p0[r]; sl->red3[wid][r][1] = p1[r]; }
    }
    __syncthreads();
    if (t < RWS * 2) {
        int r = t >> 1, c = t & 1;
        float s = 0.f;
        #pragma unroll
        for (int w = 0; w < 8; w++) s += sl->red3[w][r][c];
        sl->raw[r][c] = s + b3[c];
    }
    __syncthreads();
    if (t < RWS) {
        float r0 = sl->raw[t][0], r1 = sl->raw[t][1];
        float m = fmaxf(r0, r1);
        float e0 = expf(r0 - m), e1 = expf(r1 - m);
        float inv = 1.f / (e0 + e1);
        g_w[row0 + t][0] = e0 * inv;
        g_w[row0 + t][1] = e1 * inv;
    }
}

__device__ __forceinline__ void dev_fuse_chunk(const float* __restrict__ xg,
                                               const float* __restrict__ xa,
                                               const int* __restrict__ batch,
                                               float* __restrict__ out, int chunk) {
    size_t i0 = (size_t)chunk * 512 + threadIdx.x;
    size_t i1 = i0 + 256;
    int n0 = (int)(i0 >> 7);
    int n1 = (int)(i1 >> 7);
    int b0 = __ldg(&batch[n0]);
    int b1 = __ldg(&batch[n1]);
    float4 g0 = __ldcs(((const float4*)xg) + i0);
    float4 a0 = __ldcs(((const float4*)xa) + i0);
    float4 g1 = __ldcs(((const float4*)xg) + i1);
    float4 a1 = __ldcs(((const float4*)xa) + i1);
    float w00 = g_w[b0][0], w01 = g_w[b0][1];
    float w10 = g_w[b1][0], w11 = g_w[b1][1];
    float4 o0, o1;
    o0.x = w00 * g0.x + w01 * a0.x;
    o0.y = w00 * g0.y + w01 * a0.y;
    o0.z = w00 * g0.z + w01 * a0.z;
    o0.w = w00 * g0.w + w01 * a0.w;
    o1.x = w10 * g1.x + w11 * a1.x;
    o1.y = w10 * g1.y + w11 * a1.y;
    o1.z = w10 * g1.z + w11 * a1.z;
    o1.w = w10 * g1.w + w11 * a1.w;
    __stcs(((float4*)out) + i0, o0);
    __stcs(((float4*)out) + i1, o1);
}

// ---------------- node 1: edges (blocks 0..79) + pool tasks (80..1103) ----------
__global__ void __launch_bounds__(256) k_phase1(
    const float* __restrict__ xg, const float* __restrict__ xa,
    const int* __restrict__ edge, const int* __restrict__ batch)
{
    __shared__ __align__(16) char sm[sizeof(SmemEdge) > sizeof(SmemPool)
                                     ? sizeof(SmemEdge) : sizeof(SmemPool)];
    int bid = blockIdx.x;
    int t = threadIdx.x;

    if (bid < P1EDGE) {
        for (int task = bid; task < OFFT; task += P1EDGE)
            dev_offsets_i(batch, task * 256 + t);
        SmemEdge* se = (SmemEdge*)sm;
        for (int i = t; i < Bb; i += NTHR) se->hist[i] = 0;
        __syncthreads();
        for (int task = bid; task < EDGT; task += P1EDGE)
            dev_edge_i(edge, batch, task * 256 + t, se->hist);
        __syncthreads();
        for (int b = t; b < Bb; b += NTHR) {
            int v = se->hist[b];
            if (v) atomicAdd(&g_nedges[b], v);
        }
    } else {
        int task = bid - P1EDGE;           // 0..1023
        int b = task >> 1, half = task & 1;
        dev_pool_task(half ? xa : xg, batch, b, half, (SmemPool*)sm);
    }
}

// ---------------- node 2: persistent gemm1 + mlp2 -------------------------------
__global__ void __launch_bounds__(NTHR, 4) k_phase2(
    const float* __restrict__ W1, const float* __restrict__ b1,
    const float* __restrict__ lng, const float* __restrict__ lnb,
    const float* __restrict__ W2, const float* __restrict__ b2,
    const float* __restrict__ W3, const float* __restrict__ b3)
{
    __shared__ __align__(16) char sm[sizeof(SmemGemm)];
    int bid = blockIdx.x;

    {
        SmemGemm* sg = (SmemGemm*)sm;
        int z = bid >> 7, rem = bid & 127;
        dev_gemm1_task(W1, z, (rem & 15) * BN, (rem >> 4) * BM, sg);
    }
    gbarN(GRID2);

    if (bid < Bb / RWS) {
        SmemMlp* sl = (SmemMlp*)sm;
        dev_mlp2_task(W1, b1, lng, lnb, W2, b2, W3, b3, bid * RWS, sl);
    }
}

// ---------------- node 3: fuse ---------------------------------------------------
__global__ void __launch_bounds__(256) k_fuse(const float* __restrict__ xg,
                                              const float* __restrict__ xa,
                                              const int* __restrict__ batch,
                                              float* __restrict__ out) {
    dev_fuse_chunk(xg, xa, batch, out, blockIdx.x);
}

// ---------------- fallback kernels ----------------------------------------------
__global__ void __launch_bounds__(256) k_gemm1(const float* __restrict__ W1) {
    __shared__ __align__(16) char sm[sizeof(SmemGemm)];
    dev_gemm1_task(W1, blockIdx.z, blockIdx.x * BN, blockIdx.y * BM, (SmemGemm*)sm);
}

__global__ void __launch_bounds__(256) k_mlp2(
    const float* __restrict__ W1, const float* __restrict__ b1,
    const float* __restrict__ lng, const float* __restrict__ lnb,
    const float* __restrict__ W2, const float* __restrict__ b2,
    const float* __restrict__ W3, const float* __restrict__ b3) {
    __shared__ __align__(16) char sm[sizeof(SmemMlp)];
    dev_mlp2_task(W1, b1, lng, lnb, W2, b2, W3, b3, blockIdx.x * RWS, (SmemMlp*)sm);
}

// ---------------- launch ---------------------------------------------------------
extern "C" void kernel_launch(void* const* d_in, const int* in_sizes, int n_in,
                              void* d_out, int out_size) {
    const float* x_ggnn  = (const float*)d_in[0];
    const float* x_appnp = (const float*)d_in[1];
    const int*   edge    = (const int*)d_in[2];
    const int*   batch   = (const int*)d_in[3];
    const float* W1 = (const float*)d_in[4];
    const float* b1 = (const float*)d_in[5];
    const float* lng = (const float*)d_in[6];
    const float* lnb = (const float*)d_in[7];
    const float* W2 = (const float*)d_in[8];
    const float* b2 = (const float*)d_in[9];
    const float* W3 = (const float*)d_in[10];
    const float* b3 = (const float*)d_in[11];
    float* out = (float*)d_out;

    k_phase1<<<P1GRID, NTHR>>>(x_ggnn, x_appnp, edge, batch);

    // phase 2 needs all GRID2 blocks co-resident for the grid barrier
    int dev = 0, nsm = 0, occ = 0;
    cudaGetDevice(&dev);
    cudaDeviceGetAttribute(&nsm, cudaDevAttrMultiProcessorCount, dev);
    cudaOccupancyMaxActiveBlocksPerMultiprocessor(&occ, k_phase2, NTHR, 0);
    if (occ * nsm >= GRID2) {
        k_phase2<<<GRID2, NTHR>>>(W1, b1, lng, lnb, W2, b2, W3, b3);
    } else {
        k_gemm1<<<dim3(Hh / BN, Bb / BM, NSPLIT), 256>>>(W1);
        k_mlp2<<<Bb / RWS, 256>>>(W1, b1, lng, lnb, W2, b2, W3, b3);
    }

    k_fuse<<<FCHUNKS, 256>>>(x_ggnn, x_appnp, batch, out);
}